// round 12
// baseline (speedup 1.0000x reference)
#include <cuda_runtime.h>

// QuantumConv1d — pipelined 2-stream graph:
//   chunk batches into 4 groups of 8; ez(chunk i) on capture stream, writer(chunk i)
//   on a second stream gated by an event, so writer(i) overlaps ez(i+1..).
//   Kernels identical to the round-11 best (ez: LDS-amortized conv + inline Q;
//   writer: round-4 measured-best float4 __stcs config).

#define C_IN     80
#define L_IN     3000
#define OUT_CH   512
#define KW       3
#define TILE_L   128
#define EZTHR    128
#define WTILE    128
#define B_MAX    32
#define NCHUNK   4

__device__ float4 g_ez4[B_MAX * L_IN];     // expz per (b,l): float4 over qubits

// ===================== Kernel 1: ez (round-11, + batch offset) =====================
__global__ __launch_bounds__(EZTHR)
void ez_kernel(const float* __restrict__ x,
               const float* __restrict__ W_pre,
               const float* __restrict__ b_pre,
               const float* __restrict__ qw,
               int b0)
{
    __shared__ float x_s[C_IN][132];
    __shared__ float x_lh[C_IN];
    __shared__ float w_s[C_IN * 12];
    __shared__ float Q_s[4][16];
    __shared__ float bpre_s[4];

    const int tid = threadIdx.x;
    const int b   = b0 + blockIdx.y;
    const int l0  = blockIdx.x * TILE_L;

    if (tid < 32) {
        const int k = tid & 3;
        float sr[16], si[16];
        #pragma unroll
        for (int j = 0; j < 16; j++) { sr[j] = 0.f; si[j] = 0.f; }
        #pragma unroll
        for (int j = 0; j < 4; j++) if (j == k) sr[j] = 1.f;

        #pragma unroll
        for (int i = 0; i < 4; i++) {
            float phi = __ldg(qw + i * 3 + 0), th = __ldg(qw + i * 3 + 1), om = __ldg(qw + i * 3 + 2);
            float sh, ch; __sincosf(0.5f * th, &sh, &ch);
            float a = 0.5f * (phi + om), d = 0.5f * (phi - om);
            float sa, ca, sd, cd;
            __sincosf(a, &sa, &ca);
            __sincosf(d, &sd, &cd);
            float u00r =  ch * ca, u00i = -ch * sa;
            float u01r = -sh * cd, u01i = -sh * sd;
            float u10r =  sh * cd, u10i = -sh * sd;
            float u11r =  ch * ca, u11i =  ch * sa;
            const int s = 8 >> i;
            #pragma unroll
            for (int j = 0; j < 16; j++) {
                if ((j & s) == 0) {
                    const int j1 = j | s;
                    float ar = sr[j],  ai = si[j];
                    float br = sr[j1], bi = si[j1];
                    sr[j]  = u00r * ar - u00i * ai + u01r * br - u01i * bi;
                    si[j]  = u00r * ai + u00i * ar + u01r * bi + u01i * br;
                    sr[j1] = u10r * ar - u10i * ai + u11r * br - u11i * bi;
                    si[j1] = u10r * ai + u10i * ar + u11r * bi + u11i * br;
                }
            }
        }
        #define SWP(A,B) { float t; t=sr[A]; sr[A]=sr[B]; sr[B]=t; t=si[A]; si[A]=si[B]; si[B]=t; }
        SWP(8,12) SWP(9,13) SWP(10,14) SWP(11,15)
        SWP(4,6)  SWP(5,7)  SWP(12,14) SWP(13,15)
        SWP(2,3)  SWP(6,7)  SWP(10,11) SWP(14,15)
        #undef SWP

        float Qv[4][4];
        #pragma unroll
        for (int q = 0; q < 4; q++)
            #pragma unroll
            for (int m = 0; m < 4; m++) Qv[q][m] = 0.f;
        #pragma unroll
        for (int j = 0; j < 16; j++) {
            #pragma unroll
            for (int m = 0; m < 4; m++) {
                float arm = __shfl_sync(0xffffffffu, sr[j], m);
                float aim = __shfl_sync(0xffffffffu, si[j], m);
                float p = sr[j] * arm + si[j] * aim;
                Qv[0][m] += (j & 8) ? -p : p;
                Qv[1][m] += (j & 4) ? -p : p;
                Qv[2][m] += (j & 2) ? -p : p;
                Qv[3][m] += (j & 1) ? -p : p;
            }
        }
        if (tid < 4) {
            #pragma unroll
            for (int q = 0; q < 4; q++)
                #pragma unroll
                for (int m = 0; m < 4; m++)
                    Q_s[q][tid * 4 + m] = Qv[q][m];
        }
    } else {
        const int t = tid - 32;
        for (int i = t; i < C_IN * 12; i += EZTHR - 32) {
            int c = i / 12; int r = i - c * 12; int k = r >> 2; int q = r & 3;
            w_s[i] = W_pre[q * (C_IN * KW) + c * KW + k];
        }
        if (t < 4) bpre_s[t] = b_pre[t];

        const float* xb = x + (size_t)b * C_IN * L_IN;
        for (int i = t; i < C_IN * 32; i += EZTHR - 32) {
            int c  = i >> 5;
            int qq = i & 31;
            int l  = l0 + qq * 4;
            float4 vv;
            if (l + 3 < L_IN) {
                vv = *(const float4*)(xb + (size_t)c * L_IN + l);
            } else {
                vv.x = (l + 0 < L_IN) ? xb[(size_t)c * L_IN + l + 0] : 0.f;
                vv.y = (l + 1 < L_IN) ? xb[(size_t)c * L_IN + l + 1] : 0.f;
                vv.z = (l + 2 < L_IN) ? xb[(size_t)c * L_IN + l + 2] : 0.f;
                vv.w = (l + 3 < L_IN) ? xb[(size_t)c * L_IN + l + 3] : 0.f;
            }
            *(float4*)&x_s[c][qq * 4] = vv;
        }
        for (int c = t; c < C_IN; c += EZTHR - 32) {
            int lr = l0 + 128;
            x_s[c][128] = (lr < L_IN) ? xb[(size_t)c * L_IN + lr] : 0.f;
            int ll = l0 - 1;
            x_lh[c] = (ll >= 0) ? xb[(size_t)c * L_IN + ll] : 0.f;
        }
    }
    __syncthreads();

    const int pg   = tid >> 3;
    const int cg   = tid & 7;
    const int pos0 = pg * 8;

    float acc[8][4];
    #pragma unroll
    for (int p = 0; p < 8; p++)
        #pragma unroll
        for (int q = 0; q < 4; q++) acc[p][q] = 0.f;

    #pragma unroll
    for (int ci = 0; ci < 10; ci++) {
        const int c = cg + ci * 8;
        const float* xr = &x_s[c][0];

        float xlm1;
        if (pg > 0) xlm1 = xr[pos0 - 1];
        else        xlm1 = x_lh[c];
        float4 xq1 = *(const float4*)(xr + pos0);
        float4 xq2 = *(const float4*)(xr + pos0 + 4);
        float xlp8 = xr[pos0 + 8];

        float xwin[10] = { xlm1, xq1.x, xq1.y, xq1.z, xq1.w,
                           xq2.x, xq2.y, xq2.z, xq2.w, xlp8 };

        const float4* wr = (const float4*)&w_s[c * 12];
        float4 w0 = wr[0], w1 = wr[1], w2 = wr[2];

        #pragma unroll
        for (int p = 0; p < 8; p++) {
            acc[p][0] += w0.x * xwin[p] + w1.x * xwin[p + 1] + w2.x * xwin[p + 2];
            acc[p][1] += w0.y * xwin[p] + w1.y * xwin[p + 1] + w2.y * xwin[p + 2];
            acc[p][2] += w0.z * xwin[p] + w1.z * xwin[p + 1] + w2.z * xwin[p + 2];
            acc[p][3] += w0.w * xwin[p] + w1.w * xwin[p + 1] + w2.w * xwin[p + 2];
        }
    }

    float b4[4][4];
    {
        float rx[8][4];
        #pragma unroll
        for (int p = 0; p < 8; p++)
            #pragma unroll
            for (int q = 0; q < 4; q++)
                rx[p][q] = __shfl_xor_sync(0xffffffffu, acc[p][q], 1);
        if (cg & 1) {
            #pragma unroll
            for (int j = 0; j < 4; j++)
                #pragma unroll
                for (int q = 0; q < 4; q++) b4[j][q] = acc[2*j+1][q] + rx[2*j+1][q];
        } else {
            #pragma unroll
            for (int j = 0; j < 4; j++)
                #pragma unroll
                for (int q = 0; q < 4; q++) b4[j][q] = acc[2*j][q] + rx[2*j][q];
        }
    }
    float c2[2][4];
    {
        float rx[4][4];
        #pragma unroll
        for (int j = 0; j < 4; j++)
            #pragma unroll
            for (int q = 0; q < 4; q++)
                rx[j][q] = __shfl_xor_sync(0xffffffffu, b4[j][q], 2);
        if (cg & 2) {
            #pragma unroll
            for (int i = 0; i < 2; i++)
                #pragma unroll
                for (int q = 0; q < 4; q++) c2[i][q] = b4[2*i+1][q] + rx[2*i+1][q];
        } else {
            #pragma unroll
            for (int i = 0; i < 2; i++)
                #pragma unroll
                for (int q = 0; q < 4; q++) c2[i][q] = b4[2*i][q] + rx[2*i][q];
        }
    }
    float v0, v1, v2, v3;
    {
        float rx[2][4];
        #pragma unroll
        for (int i = 0; i < 2; i++)
            #pragma unroll
            for (int q = 0; q < 4; q++)
                rx[i][q] = __shfl_xor_sync(0xffffffffu, c2[i][q], 4);
        if (cg & 4) {
            v0 = c2[1][0] + rx[1][0]; v1 = c2[1][1] + rx[1][1];
            v2 = c2[1][2] + rx[1][2]; v3 = c2[1][3] + rx[1][3];
        } else {
            v0 = c2[0][0] + rx[0][0]; v1 = c2[0][1] + rx[0][1];
            v2 = c2[0][2] + rx[0][2]; v3 = c2[0][3] + rx[0][3];
        }
    }
    v0 += bpre_s[0]; v1 += bpre_s[1]; v2 += bpre_s[2]; v3 += bpre_s[3];

    const int l = l0 + tid;
    if (l >= L_IN) return;

    const float inv = __frcp_rn(v0 * v0 + v1 * v1 + v2 * v2 + v3 * v3);
    float e[4];
    #pragma unroll
    for (int q = 0; q < 4; q++) {
        const float* Qr = &Q_s[q][0];
        float s;
        s  = v0 * (Qr[0]  * v0 + Qr[1]  * v1 + Qr[2]  * v2 + Qr[3]  * v3);
        s += v1 * (Qr[4]  * v0 + Qr[5]  * v1 + Qr[6]  * v2 + Qr[7]  * v3);
        s += v2 * (Qr[8]  * v0 + Qr[9]  * v1 + Qr[10] * v2 + Qr[11] * v3);
        s += v3 * (Qr[12] * v0 + Qr[13] * v1 + Qr[14] * v2 + Qr[15] * v3);
        e[q] = s * inv;
    }
    g_ez4[(size_t)b * L_IN + l] = make_float4(e[0], e[1], e[2], e[3]);
}

// ===================== Kernel 2: writer (round-4 config, + batch offset) ==============
__global__ __launch_bounds__(512)
void write_kernel(const float* __restrict__ W_post,
                  const float* __restrict__ b_post,
                  float* __restrict__ out,
                  int b0)
{
    const int tid  = threadIdx.x;
    const int b    = b0 + blockIdx.y;
    const int l0   = blockIdx.x * WTILE;
    const int lane = tid & 31;
    const int wrp  = tid >> 5;
    const int l4   = l0 + lane * 4;
    if (l4 >= L_IN) return;

    const float4* ezp = &g_ez4[(size_t)b * L_IN + l4];
    const float4 e0 = __ldg(ezp + 0);
    const float4 e1 = __ldg(ezp + 1);
    const float4 e2 = __ldg(ezp + 2);
    const float4 e3 = __ldg(ezp + 3);

    float* outb = out + (size_t)b * OUT_CH * L_IN;

    #pragma unroll 8
    for (int o = wrp; o < OUT_CH; o += 16) {
        const float4 wp = __ldg((const float4*)(W_post + o * 4));
        const float  bp = __ldg(b_post + o);
        float4 r;
        r.x = fmaf(wp.x, e0.x, fmaf(wp.y, e0.y, fmaf(wp.z, e0.z, fmaf(wp.w, e0.w, bp))));
        r.y = fmaf(wp.x, e1.x, fmaf(wp.y, e1.y, fmaf(wp.z, e1.z, fmaf(wp.w, e1.w, bp))));
        r.z = fmaf(wp.x, e2.x, fmaf(wp.y, e2.y, fmaf(wp.z, e2.z, fmaf(wp.w, e2.w, bp))));
        r.w = fmaf(wp.x, e3.x, fmaf(wp.y, e3.y, fmaf(wp.z, e3.z, fmaf(wp.w, e3.w, bp))));
        __stcs((float4*)(outb + (size_t)o * L_IN + l4), r);
    }
}

// ===================== Host: pipelined fork/join launch =====================
static cudaStream_t g_s2 = nullptr;
static cudaEvent_t  g_ev[NCHUNK];
static cudaEvent_t  g_join = nullptr;

extern "C" void kernel_launch(void* const* d_in, const int* in_sizes, int n_in,
                              void* d_out, int out_size)
{
    const float* x      = (const float*)d_in[0];
    const float* W_pre  = (const float*)d_in[1];
    const float* b_pre  = (const float*)d_in[2];
    const float* W_post = (const float*)d_in[3];
    const float* b_post = (const float*)d_in[4];
    const float* qw     = (const float*)d_in[5];
    float* out = (float*)d_out;

    if (!g_s2) {   // one-time host-side resource init (no device allocations)
        cudaStreamCreateWithFlags(&g_s2, cudaStreamNonBlocking);
        for (int i = 0; i < NCHUNK; i++)
            cudaEventCreateWithFlags(&g_ev[i], cudaEventDisableTiming);
        cudaEventCreateWithFlags(&g_join, cudaEventDisableTiming);
    }

    const int B = in_sizes[0] / (C_IN * L_IN);                  // 32
    const int n_tiles = (L_IN + TILE_L - 1) / TILE_L;           // 24
    const int bchunk  = (B + NCHUNK - 1) / NCHUNK;              // 8

    // producers on the capture (default) stream, each followed by an event
    for (int i = 0; i < NCHUNK; i++) {
        const int b0 = i * bchunk;
        const int nb = (b0 + bchunk <= B) ? bchunk : (B - b0);
        if (nb <= 0) break;
        dim3 g1(n_tiles, nb);
        ez_kernel<<<g1, EZTHR>>>(x, W_pre, b_pre, qw, b0);
        cudaEventRecord(g_ev[i], 0);
    }

    // consumers on the second stream, gated per-chunk (fork via first wait)
    for (int i = 0; i < NCHUNK; i++) {
        const int b0 = i * bchunk;
        const int nb = (b0 + bchunk <= B) ? bchunk : (B - b0);
        if (nb <= 0) break;
        cudaStreamWaitEvent(g_s2, g_ev[i], 0);
        dim3 g2(n_tiles, nb);
        write_kernel<<<g2, 512, 0, g_s2>>>(W_post, b_post, out, b0);
    }

    // join back onto the capture stream
    cudaEventRecord(g_join, g_s2);
    cudaStreamWaitEvent(0, g_join, 0);
}

// round 13
// speedup vs baseline: 1.4864x; 1.4864x over previous
#include <cuda_runtime.h>

// QuantumConv1d, 2-kernel pipeline. Round-13 focus: kill ez register spills.
//  K1 (ez): 256 thr, thread (pos, cg) does 1 position x 40 interleaved channels
//      (~25 live regs, no arrays), shfl_xor(1) merge, even lane stores float4 expz.
//      Warp0 folds circuit -> Q forms (spill-tolerant, overlapped with staging).
//      __launch_bounds__(256,4) caps regs at 64 so the conv path cannot spill.
//  K2 (writer): round-4 measured-best: 512 thr, grid(24,32), float4 __stcs,
//      196.6MB streaming stores (the roofline term).

#define C_IN     80
#define L_IN     3000
#define OUT_CH   512
#define KW       3
#define TILE_L   128
#define EZTHR    256
#define WTILE    128
#define B_MAX    32

__device__ float4 g_ez4[B_MAX * L_IN];     // expz per (b,l): float4 over qubits

// ===================== Kernel 1: ez =====================
__global__ __launch_bounds__(EZTHR, 4)
void ez_kernel(const float* __restrict__ x,
               const float* __restrict__ W_pre,
               const float* __restrict__ b_pre,
               const float* __restrict__ qw)
{
    __shared__ float x_s[C_IN][132];        // j: 0..129 used; j=0 <-> l0-1
    __shared__ float w_s[C_IN * 12];        // [c][k][q]
    __shared__ float Q_s[4][16];
    __shared__ float bpre_s[4];

    const int tid = threadIdx.x;
    const int b   = blockIdx.y;
    const int l0  = blockIdx.x * TILE_L;

    // ======== Phase 0: warp 0 folds Q; warps 1-7 stage x + weights ========
    if (tid < 32) {
        const int k = tid & 3;
        float sr[16], si[16];
        #pragma unroll
        for (int j = 0; j < 16; j++) { sr[j] = 0.f; si[j] = 0.f; }
        #pragma unroll
        for (int j = 0; j < 4; j++) if (j == k) sr[j] = 1.f;

        #pragma unroll
        for (int i = 0; i < 4; i++) {
            float phi = __ldg(qw + i * 3 + 0), th = __ldg(qw + i * 3 + 1), om = __ldg(qw + i * 3 + 2);
            float sh, ch; __sincosf(0.5f * th, &sh, &ch);
            float a = 0.5f * (phi + om), d = 0.5f * (phi - om);
            float sa, ca, sd, cd;
            __sincosf(a, &sa, &ca);
            __sincosf(d, &sd, &cd);
            float u00r =  ch * ca, u00i = -ch * sa;
            float u01r = -sh * cd, u01i = -sh * sd;
            float u10r =  sh * cd, u10i = -sh * sd;
            float u11r =  ch * ca, u11i =  ch * sa;
            const int s = 8 >> i;
            #pragma unroll
            for (int j = 0; j < 16; j++) {
                if ((j & s) == 0) {
                    const int j1 = j | s;
                    float ar = sr[j],  ai = si[j];
                    float br = sr[j1], bi = si[j1];
                    sr[j]  = u00r * ar - u00i * ai + u01r * br - u01i * bi;
                    si[j]  = u00r * ai + u00i * ar + u01r * bi + u01i * br;
                    sr[j1] = u10r * ar - u10i * ai + u11r * br - u11i * bi;
                    si[j1] = u10r * ai + u10i * ar + u11r * bi + u11i * br;
                }
            }
        }
        #define SWP(A,B) { float t; t=sr[A]; sr[A]=sr[B]; sr[B]=t; t=si[A]; si[A]=si[B]; si[B]=t; }
        SWP(8,12) SWP(9,13) SWP(10,14) SWP(11,15)   // cnot(0,1)
        SWP(4,6)  SWP(5,7)  SWP(12,14) SWP(13,15)   // cnot(1,2)
        SWP(2,3)  SWP(6,7)  SWP(10,11) SWP(14,15)   // cnot(2,3)
        #undef SWP

        float Qv[4][4];
        #pragma unroll
        for (int q = 0; q < 4; q++)
            #pragma unroll
            for (int m = 0; m < 4; m++) Qv[q][m] = 0.f;
        #pragma unroll
        for (int j = 0; j < 16; j++) {
            #pragma unroll
            for (int m = 0; m < 4; m++) {
                float arm = __shfl_sync(0xffffffffu, sr[j], m);
                float aim = __shfl_sync(0xffffffffu, si[j], m);
                float p = sr[j] * arm + si[j] * aim;
                Qv[0][m] += (j & 8) ? -p : p;
                Qv[1][m] += (j & 4) ? -p : p;
                Qv[2][m] += (j & 2) ? -p : p;
                Qv[3][m] += (j & 1) ? -p : p;
            }
        }
        if (tid < 4) {
            #pragma unroll
            for (int q = 0; q < 4; q++)
                #pragma unroll
                for (int m = 0; m < 4; m++)
                    Q_s[q][tid * 4 + m] = Qv[q][m];
            bpre_s[tid] = b_pre[tid];
        }
    } else {
        const int t = tid - 32;                     // 0..223
        for (int i = t; i < C_IN * 12; i += EZTHR - 32) {
            int c = i / 12; int r = i - c * 12; int k = r >> 2; int q = r & 3;
            w_s[i] = W_pre[q * (C_IN * KW) + c * KW + k];
        }
        const float* xb = x + (size_t)b * C_IN * L_IN;
        // interior: j = 1..128 <-> l = l0..l0+127, 80 rows x 32 aligned float4
        for (int i = t; i < C_IN * 32; i += EZTHR - 32) {
            int c  = i >> 5;
            int qq = i & 31;
            int l  = l0 + qq * 4;
            float4 vv;
            if (l + 3 < L_IN) {
                vv = *(const float4*)(xb + (size_t)c * L_IN + l);
            } else {
                vv.x = (l + 0 < L_IN) ? xb[(size_t)c * L_IN + l + 0] : 0.f;
                vv.y = (l + 1 < L_IN) ? xb[(size_t)c * L_IN + l + 1] : 0.f;
                vv.z = (l + 2 < L_IN) ? xb[(size_t)c * L_IN + l + 2] : 0.f;
                vv.w = (l + 3 < L_IN) ? xb[(size_t)c * L_IN + l + 3] : 0.f;
            }
            x_s[c][1 + qq * 4] = vv.x;     // unaligned dest: scalar writes
            x_s[c][2 + qq * 4] = vv.y;
            x_s[c][3 + qq * 4] = vv.z;
            x_s[c][4 + qq * 4] = vv.w;
        }
        // halos: j=0 <-> l0-1, j=129 <-> l0+128
        for (int c = t; c < C_IN; c += EZTHR - 32) {
            int ll = l0 - 1;
            x_s[c][0]   = (ll >= 0) ? xb[(size_t)c * L_IN + ll] : 0.f;
            int lr = l0 + 128;
            x_s[c][129] = (lr < L_IN) ? xb[(size_t)c * L_IN + lr] : 0.f;
        }
    }
    __syncthreads();

    // ======== Phase 1: 1 position x 40 interleaved channels per thread ========
    const int pos = tid >> 1;                   // 0..127
    const int cg  = tid & 1;                    // 0..1

    float v0 = 0.f, v1 = 0.f, v2 = 0.f, v3 = 0.f;
    #pragma unroll
    for (int ci = 0; ci < 40; ci++) {
        const int c = cg + ci * 2;              // interleaved halves
        float xa = x_s[c][pos];                 // l-1
        float xb1 = x_s[c][pos + 1];            // l
        float xc = x_s[c][pos + 2];             // l+1
        const float4* wr = (const float4*)&w_s[c * 12];
        float4 w0 = wr[0], w1 = wr[1], w2 = wr[2];
        v0 += w0.x * xa + w1.x * xb1 + w2.x * xc;
        v1 += w0.y * xa + w1.y * xb1 + w2.y * xc;
        v2 += w0.z * xa + w1.z * xb1 + w2.z * xc;
        v3 += w0.w * xa + w1.w * xb1 + w2.w * xc;
    }
    // merge the two channel halves (lanes 2p, 2p+1)
    v0 += __shfl_xor_sync(0xffffffffu, v0, 1);
    v1 += __shfl_xor_sync(0xffffffffu, v1, 1);
    v2 += __shfl_xor_sync(0xffffffffu, v2, 1);
    v3 += __shfl_xor_sync(0xffffffffu, v3, 1);

    const int l = l0 + pos;
    if (cg == 0 && l < L_IN) {
        v0 += bpre_s[0]; v1 += bpre_s[1]; v2 += bpre_s[2]; v3 += bpre_s[3];
        const float inv = __frcp_rn(v0 * v0 + v1 * v1 + v2 * v2 + v3 * v3);
        float e[4];
        #pragma unroll
        for (int q = 0; q < 4; q++) {
            const float* Qr = &Q_s[q][0];
            float s;
            s  = v0 * (Qr[0]  * v0 + Qr[1]  * v1 + Qr[2]  * v2 + Qr[3]  * v3);
            s += v1 * (Qr[4]  * v0 + Qr[5]  * v1 + Qr[6]  * v2 + Qr[7]  * v3);
            s += v2 * (Qr[8]  * v0 + Qr[9]  * v1 + Qr[10] * v2 + Qr[11] * v3);
            s += v3 * (Qr[12] * v0 + Qr[13] * v1 + Qr[14] * v2 + Qr[15] * v3);
            e[q] = s * inv;
        }
        g_ez4[(size_t)b * L_IN + l] = make_float4(e[0], e[1], e[2], e[3]);
    }
}

// ===================== Kernel 2: writer (round-4 measured-best, unchanged) =====================
__global__ __launch_bounds__(512)
void write_kernel(const float* __restrict__ W_post,
                  const float* __restrict__ b_post,
                  float* __restrict__ out)
{
    const int tid  = threadIdx.x;
    const int b    = blockIdx.y;
    const int l0   = blockIdx.x * WTILE;
    const int lane = tid & 31;
    const int wrp  = tid >> 5;                  // 0..15
    const int l4   = l0 + lane * 4;
    if (l4 >= L_IN) return;                     // L_IN % 4 == 0: no straddle

    const float4* ezp = &g_ez4[(size_t)b * L_IN + l4];
    const float4 e0 = __ldg(ezp + 0);
    const float4 e1 = __ldg(ezp + 1);
    const float4 e2 = __ldg(ezp + 2);
    const float4 e3 = __ldg(ezp + 3);

    float* outb = out + (size_t)b * OUT_CH * L_IN;

    #pragma unroll 8
    for (int o = wrp; o < OUT_CH; o += 16) {
        const float4 wp = __ldg((const float4*)(W_post + o * 4));
        const float  bp = __ldg(b_post + o);
        float4 r;
        r.x = fmaf(wp.x, e0.x, fmaf(wp.y, e0.y, fmaf(wp.z, e0.z, fmaf(wp.w, e0.w, bp))));
        r.y = fmaf(wp.x, e1.x, fmaf(wp.y, e1.y, fmaf(wp.z, e1.z, fmaf(wp.w, e1.w, bp))));
        r.z = fmaf(wp.x, e2.x, fmaf(wp.y, e2.y, fmaf(wp.z, e2.z, fmaf(wp.w, e2.w, bp))));
        r.w = fmaf(wp.x, e3.x, fmaf(wp.y, e3.y, fmaf(wp.z, e3.z, fmaf(wp.w, e3.w, bp))));
        __stcs((float4*)(outb + (size_t)o * L_IN + l4), r);
    }
}

extern "C" void kernel_launch(void* const* d_in, const int* in_sizes, int n_in,
                              void* d_out, int out_size)
{
    const float* x      = (const float*)d_in[0];
    const float* W_pre  = (const float*)d_in[1];
    const float* b_pre  = (const float*)d_in[2];
    const float* W_post = (const float*)d_in[3];
    const float* b_post = (const float*)d_in[4];
    const float* qw     = (const float*)d_in[5];
    float* out = (float*)d_out;

    const int B = in_sizes[0] / (C_IN * L_IN);                  // 32
    const int n_tiles = (L_IN + TILE_L - 1) / TILE_L;           // 24

    dim3 g1(n_tiles, B);
    ez_kernel<<<g1, EZTHR>>>(x, W_pre, b_pre, qw);

    dim3 g2(n_tiles, B);
    write_kernel<<<g2, 512>>>(W_post, b_post, out);
}